// round 1
// baseline (speedup 1.0000x reference)
#include <cuda_runtime.h>
#include <math.h>

#define BATCH 2
#define SEQ 2048
#define DM 1024
#define NH 16
#define DH 64

// Scratch (device globals: allocation-free per harness rules)
__device__ float g_q[BATCH * SEQ * DM];
__device__ float g_k[BATCH * SEQ * DM];
__device__ float g_v[BATCH * SEQ * DM];
__device__ float g_z[BATCH * SEQ * DM];

// XOR swizzle for 64x64 fp32 smem tiles: conflict-free for row-vector and
// col-vector access patterns used below. addr = r*64 + (c ^ sw(r)),
// sw(r) = (r&31) ^ (r>>5) keeps bit5 information so 16 lanes reading
// 16 distinct rows at fixed c land in 16 distinct banks.
__device__ __forceinline__ int SWZ(int r, int c) {
    return r * 64 + (c ^ ((r ^ (r >> 5)) & 31));
}

// ---------------------------------------------------------------------------
// QKV projection: C[4096,1024] = X[4096,1024] @ W[h,d,e] (+bias[1024])
// blockIdx.z in {0,1,2} selects (X,W,b,C) for Q/K/V.
// Tile 64x64, K-tile 32, 256 threads, 4x4 per thread.
// ---------------------------------------------------------------------------
__global__ __launch_bounds__(256)
void qkv_gemm_kernel(const float* __restrict__ xq, const float* __restrict__ xk,
                     const float* __restrict__ xv,
                     const float* __restrict__ wq, const float* __restrict__ wk,
                     const float* __restrict__ wv,
                     const float* __restrict__ bq, const float* __restrict__ bk,
                     const float* __restrict__ bv)
{
    __shared__ float As[64 * 32];
    __shared__ float Bs[32 * 64];

    const int z = blockIdx.z;
    const float* __restrict__ X = (z == 0) ? xq : (z == 1) ? xk : xv;
    const float* __restrict__ W = (z == 0) ? wq : (z == 1) ? wk : wv;
    const float* __restrict__ B = (z == 0) ? bq : (z == 1) ? bk : bv;
    float* __restrict__ C       = (z == 0) ? g_q : (z == 1) ? g_k : g_v;

    const int t  = threadIdx.x;
    const int tx = t & 15;
    const int ty = t >> 4;
    const int m0 = blockIdx.y * 64;
    const int n0 = blockIdx.x * 64;

    // n0 is 64-aligned => entire N-tile is one head. W[h][k][e] rows stride 64.
    const int h = n0 >> 6;
    const float* __restrict__ Wb = W + (size_t)h * DM * DH;

    float acc[4][4] = {};

    for (int k0 = 0; k0 < DM; k0 += 32) {
        __syncthreads();
        // A tile 64x32 (coalesced rows of 32 floats)
        {
            int kk = t & 31, r = t >> 5;  // 8 rows per pass
            #pragma unroll
            for (int i = 0; i < 8; i++)
                As[(r + 8 * i) * 32 + kk] =
                    X[(size_t)(m0 + r + 8 * i) * DM + k0 + kk];
        }
        // B tile 32x64 (coalesced rows of 64 floats)
        {
            int n = t & 63, kr = t >> 6;  // 4 rows per pass
            #pragma unroll
            for (int i = 0; i < 8; i++)
                Bs[(kr + 4 * i) * 64 + n] =
                    Wb[(size_t)(k0 + kr + 4 * i) * DH + n];
        }
        __syncthreads();
        #pragma unroll
        for (int kk = 0; kk < 32; kk++) {
            float a0 = As[(ty * 4 + 0) * 32 + kk];
            float a1 = As[(ty * 4 + 1) * 32 + kk];
            float a2 = As[(ty * 4 + 2) * 32 + kk];
            float a3 = As[(ty * 4 + 3) * 32 + kk];
            float4 b = *(const float4*)&Bs[kk * 64 + tx * 4];
            acc[0][0] += a0 * b.x; acc[0][1] += a0 * b.y; acc[0][2] += a0 * b.z; acc[0][3] += a0 * b.w;
            acc[1][0] += a1 * b.x; acc[1][1] += a1 * b.y; acc[1][2] += a1 * b.z; acc[1][3] += a1 * b.w;
            acc[2][0] += a2 * b.x; acc[2][1] += a2 * b.y; acc[2][2] += a2 * b.z; acc[2][3] += a2 * b.w;
            acc[3][0] += a3 * b.x; acc[3][1] += a3 * b.y; acc[3][2] += a3 * b.z; acc[3][3] += a3 * b.w;
        }
    }

    #pragma unroll
    for (int i = 0; i < 4; i++) {
        int m = m0 + ty * 4 + i;
        #pragma unroll
        for (int j = 0; j < 4; j++) {
            int n = n0 + tx * 4 + j;
            C[(size_t)m * DM + n] = acc[i][j] + B[n];
        }
    }
}

// ---------------------------------------------------------------------------
// Output projection: out[4096,1024] = Z[4096,1024] @ W_O[1024,1024] + b_O
// W_O[h,e,d] reshapes to a plain row-major [1024,1024].
// ---------------------------------------------------------------------------
__global__ __launch_bounds__(256)
void out_gemm_kernel(const float* __restrict__ W, const float* __restrict__ bias,
                     float* __restrict__ C)
{
    __shared__ float As[64 * 32];
    __shared__ float Bs[32 * 64];

    const int t  = threadIdx.x;
    const int tx = t & 15;
    const int ty = t >> 4;
    const int m0 = blockIdx.y * 64;
    const int n0 = blockIdx.x * 64;
    const float* __restrict__ X  = g_z;
    const float* __restrict__ Wb = W + n0;

    float acc[4][4] = {};

    for (int k0 = 0; k0 < DM; k0 += 32) {
        __syncthreads();
        {
            int kk = t & 31, r = t >> 5;
            #pragma unroll
            for (int i = 0; i < 8; i++)
                As[(r + 8 * i) * 32 + kk] =
                    X[(size_t)(m0 + r + 8 * i) * DM + k0 + kk];
        }
        {
            int n = t & 63, kr = t >> 6;
            #pragma unroll
            for (int i = 0; i < 8; i++)
                Bs[(kr + 4 * i) * 64 + n] =
                    Wb[(size_t)(k0 + kr + 4 * i) * DM + n];
        }
        __syncthreads();
        #pragma unroll
        for (int kk = 0; kk < 32; kk++) {
            float a0 = As[(ty * 4 + 0) * 32 + kk];
            float a1 = As[(ty * 4 + 1) * 32 + kk];
            float a2 = As[(ty * 4 + 2) * 32 + kk];
            float a3 = As[(ty * 4 + 3) * 32 + kk];
            float4 b = *(const float4*)&Bs[kk * 64 + tx * 4];
            acc[0][0] += a0 * b.x; acc[0][1] += a0 * b.y; acc[0][2] += a0 * b.z; acc[0][3] += a0 * b.w;
            acc[1][0] += a1 * b.x; acc[1][1] += a1 * b.y; acc[1][2] += a1 * b.z; acc[1][3] += a1 * b.w;
            acc[2][0] += a2 * b.x; acc[2][1] += a2 * b.y; acc[2][2] += a2 * b.z; acc[2][3] += a2 * b.w;
            acc[3][0] += a3 * b.x; acc[3][1] += a3 * b.y; acc[3][2] += a3 * b.z; acc[3][3] += a3 * b.w;
        }
    }

    #pragma unroll
    for (int i = 0; i < 4; i++) {
        int m = m0 + ty * 4 + i;
        #pragma unroll
        for (int j = 0; j < 4; j++) {
            int n = n0 + tx * 4 + j;
            C[(size_t)m * DM + n] = acc[i][j] + bias[n];
        }
    }
}

// ---------------------------------------------------------------------------
// Causal flash attention (fp32, online softmax).
// Grid: (qblock=32, head=16, batch=2). Block: 256 threads.
// Q tile 64 rows resident; stream 64-key K/V tiles up to the diagonal.
// smem: Qs (64x64) + KPs (K tile, reused for P tile) + Vs = exactly 48 KB.
// Thread (tx,ty): score rows ty*4+[0,4), score cols (and out dims) tx*4+[0,4).
// ---------------------------------------------------------------------------
__global__ __launch_bounds__(256)
void attn_kernel()
{
    __shared__ float Qs[64 * 64];
    __shared__ float KPs[64 * 64];
    __shared__ float Vs[64 * 64];

    const int t  = threadIdx.x;
    const int tx = t & 15;
    const int ty = t >> 4;
    const int qb = blockIdx.x;
    const int h  = blockIdx.y;
    const int b  = blockIdx.z;
    const int q0 = qb * 64;

    // Load Q tile (swizzled)
    {
        int d = t & 63, r = t >> 6;
        #pragma unroll
        for (int i = 0; i < 16; i++) {
            int rr = r + 4 * i;
            Qs[SWZ(rr, d)] =
                g_q[(size_t)(b * SEQ + q0 + rr) * DM + h * DH + d];
        }
    }

    float acc[4][4] = {};
    float m_i[4], l_i[4];
    #pragma unroll
    for (int i = 0; i < 4; i++) { m_i[i] = -1e30f; l_i[i] = 0.0f; }

    const float scale = 0.125f;  // 1/sqrt(64)

    for (int kb = 0; kb <= qb; kb++) {
        const int k0 = kb * 64;
        __syncthreads();
        // Load K and V tiles (swizzled, coalesced)
        {
            int d = t & 63, r = t >> 6;
            #pragma unroll
            for (int i = 0; i < 16; i++) {
                int rr = r + 4 * i;
                size_t g = (size_t)(b * SEQ + k0 + rr) * DM + h * DH + d;
                KPs[SWZ(rr, d)] = g_k[g];
                Vs[SWZ(rr, d)]  = g_v[g];
            }
        }
        __syncthreads();

        // S = Q @ K^T (4x4 per thread)
        float s[4][4] = {};
        #pragma unroll 8
        for (int d = 0; d < 64; d++) {
            float a0 = Qs[SWZ(ty * 4 + 0, d)];
            float a1 = Qs[SWZ(ty * 4 + 1, d)];
            float a2 = Qs[SWZ(ty * 4 + 2, d)];
            float a3 = Qs[SWZ(ty * 4 + 3, d)];
            float c0 = KPs[SWZ(tx * 4 + 0, d)];
            float c1 = KPs[SWZ(tx * 4 + 1, d)];
            float c2 = KPs[SWZ(tx * 4 + 2, d)];
            float c3 = KPs[SWZ(tx * 4 + 3, d)];
            s[0][0] += a0 * c0; s[0][1] += a0 * c1; s[0][2] += a0 * c2; s[0][3] += a0 * c3;
            s[1][0] += a1 * c0; s[1][1] += a1 * c1; s[1][2] += a1 * c2; s[1][3] += a1 * c3;
            s[2][0] += a2 * c0; s[2][1] += a2 * c1; s[2][2] += a2 * c2; s[2][3] += a2 * c3;
            s[3][0] += a3 * c0; s[3][1] += a3 * c1; s[3][2] += a3 * c2; s[3][3] += a3 * c3;
        }

        // Scale + causal mask (only the diagonal tile has masked entries)
        #pragma unroll
        for (int i = 0; i < 4; i++) {
            int qg = q0 + ty * 4 + i;
            #pragma unroll
            for (int j = 0; j < 4; j++) {
                int kg = k0 + tx * 4 + j;
                float v = s[i][j] * scale;
                s[i][j] = (kg > qg) ? -1e9f : v;
            }
        }

        // Online softmax update (row groups = 16 lanes sharing ty)
        #pragma unroll
        for (int i = 0; i < 4; i++) {
            float mx = fmaxf(fmaxf(s[i][0], s[i][1]), fmaxf(s[i][2], s[i][3]));
            #pragma unroll
            for (int o = 8; o >= 1; o >>= 1)
                mx = fmaxf(mx, __shfl_xor_sync(0xffffffffu, mx, o, 16));
            float m_new = fmaxf(m_i[i], mx);
            float corr  = __expf(m_i[i] - m_new);
            m_i[i] = m_new;
            l_i[i] *= corr;
            #pragma unroll
            for (int j = 0; j < 4; j++) acc[i][j] *= corr;
            float rs = 0.0f;
            #pragma unroll
            for (int j = 0; j < 4; j++) {
                float p = __expf(s[i][j] - m_new);
                s[i][j] = p;
                rs += p;
            }
            #pragma unroll
            for (int o = 8; o >= 1; o >>= 1)
                rs += __shfl_xor_sync(0xffffffffu, rs, o, 16);
            l_i[i] += rs;
        }

        __syncthreads();  // all K reads complete before P overwrites KPs
        #pragma unroll
        for (int i = 0; i < 4; i++)
            #pragma unroll
            for (int j = 0; j < 4; j++)
                KPs[SWZ(ty * 4 + i, tx * 4 + j)] = s[i][j];
        __syncthreads();

        // acc += P @ V
        #pragma unroll 8
        for (int kc = 0; kc < 64; kc++) {
            float p0 = KPs[SWZ(ty * 4 + 0, kc)];
            float p1 = KPs[SWZ(ty * 4 + 1, kc)];
            float p2 = KPs[SWZ(ty * 4 + 2, kc)];
            float p3 = KPs[SWZ(ty * 4 + 3, kc)];
            float v0 = Vs[SWZ(kc, tx * 4 + 0)];
            float v1 = Vs[SWZ(kc, tx * 4 + 1)];
            float v2 = Vs[SWZ(kc, tx * 4 + 2)];
            float v3 = Vs[SWZ(kc, tx * 4 + 3)];
            acc[0][0] += p0 * v0; acc[0][1] += p0 * v1; acc[0][2] += p0 * v2; acc[0][3] += p0 * v3;
            acc[1][0] += p1 * v0; acc[1][1] += p1 * v1; acc[1][2] += p1 * v2; acc[1][3] += p1 * v3;
            acc[2][0] += p2 * v0; acc[2][1] += p2 * v1; acc[2][2] += p2 * v2; acc[2][3] += p2 * v3;
            acc[3][0] += p3 * v0; acc[3][1] += p3 * v1; acc[3][2] += p3 * v2; acc[3][3] += p3 * v3;
        }
    }

    // Normalize and store z[b, q, h, e]
    #pragma unroll
    for (int i = 0; i < 4; i++) {
        float inv = 1.0f / l_i[i];
        int q = q0 + ty * 4 + i;
        #pragma unroll
        for (int j = 0; j < 4; j++) {
            int d = tx * 4 + j;
            g_z[(size_t)(b * SEQ + q) * DM + h * DH + d] = acc[i][j] * inv;
        }
    }
}

// ---------------------------------------------------------------------------
extern "C" void kernel_launch(void* const* d_in, const int* in_sizes, int n_in,
                              void* d_out, int out_size)
{
    const float* qin = (const float*)d_in[0];
    const float* kin = (const float*)d_in[1];
    const float* vin = (const float*)d_in[2];
    const float* WQ  = (const float*)d_in[3];
    const float* WK  = (const float*)d_in[4];
    const float* WV  = (const float*)d_in[5];
    const float* WO  = (const float*)d_in[6];
    const float* bQ  = (const float*)d_in[7];
    const float* bK  = (const float*)d_in[8];
    const float* bV  = (const float*)d_in[9];
    const float* bO  = (const float*)d_in[10];
    float* out = (float*)d_out;

    dim3 gg(DM / 64, (BATCH * SEQ) / 64, 3);   // 16 x 64 x 3
    qkv_gemm_kernel<<<gg, 256>>>(qin, kin, vin, WQ, WK, WV, bQ, bK, bV);

    attn_kernel<<<dim3(SEQ / 64, NH, BATCH), 256>>>();

    dim3 go(DM / 64, (BATCH * SEQ) / 64);      // 16 x 64
    out_gemm_kernel<<<go, 256>>>(WO, bO, out);
}